// round 1
// baseline (speedup 1.0000x reference)
#include <cuda_runtime.h>
#include <math.h>

// Problem dims
#define NB 32
#define NL 4096
#define NC 64
#define ND 128
#define NK 2048   // TOPK = L/2

// ---------------- device scratch (no allocations allowed) ----------------
__device__ unsigned int  g_su[NB * NL];        // order-transformed scores
__device__ unsigned char g_mask[NB * NL];      // selected rows
__device__ float         g_part[NB * 64 * ND]; // per-(batch,tile) partial sums
__device__ float         g_agg[NB * ND];       // per-batch gelu sums

// order-preserving float -> uint (ascending)
__device__ __forceinline__ unsigned int f2u(float f) {
    unsigned int b = __float_as_uint(f);
    return (b & 0x80000000u) ? ~b : (b | 0x80000000u);
}

__device__ __forceinline__ float gelu_exact(float h) {
    return 0.5f * h * (1.0f + erff(h * 0.70710678118654752440f));
}

// ---------------- A1: scores = x . score_w + score_b -----------------------
__global__ __launch_bounds__(256) void score_kernel(const float* __restrict__ x,
                                                    const float* __restrict__ sw,
                                                    const float* __restrict__ sb) {
    __shared__ float s_w[NC];
    if (threadIdx.x < NC) s_w[threadIdx.x] = sw[threadIdx.x];
    __syncthreads();
    int r = blockIdx.x * 256 + threadIdx.x;   // 0..131071
    const float4* xr = (const float4*)(x + (size_t)r * NC);
    float acc = 0.f;
#pragma unroll
    for (int i = 0; i < 16; i++) {
        float4 v = xr[i];
        acc = fmaf(v.x, s_w[4 * i + 0], acc);
        acc = fmaf(v.y, s_w[4 * i + 1], acc);
        acc = fmaf(v.z, s_w[4 * i + 2], acc);
        acc = fmaf(v.w, s_w[4 * i + 3], acc);
    }
    g_su[r] = f2u(acc + sb[0]);
}

// ---------------- A2: per-batch exact top-NK selection (radix select) ------
__global__ __launch_bounds__(256) void select_kernel() {
    __shared__ unsigned int su[NL];
    __shared__ int hist[256];
    __shared__ unsigned int sh_prefix;
    __shared__ int sh_kth;
    __shared__ int sh_ties;
    int b = blockIdx.x;
    int tid = threadIdx.x;
    for (int l = tid; l < NL; l += 256) su[l] = g_su[b * NL + l];
    if (tid == 0) { sh_prefix = 0u; sh_kth = NK; sh_ties = 0; }
    __syncthreads();
    unsigned int decided = 0u;
    for (int pass = 0; pass < 4; pass++) {
        int shift = 24 - pass * 8;
        hist[tid] = 0;
        __syncthreads();
        unsigned int prefix = sh_prefix;
        for (int l = tid; l < NL; l += 256) {
            unsigned int u = su[l];
            bool p = ((u & decided) == prefix);
            // non-participants get unique sentinel bins -> singleton groups
            unsigned int bin = p ? ((u >> shift) & 255u) : (0x1000u + (unsigned)(tid & 31));
            unsigned int grp = __match_any_sync(0xffffffffu, bin);
            int leader = __ffs(grp) - 1;
            if (p && (tid & 31) == leader) atomicAdd(&hist[bin], __popc(grp));
        }
        __syncthreads();
        if (tid == 0) {
            int kth = sh_kth;
            int c = 0; int bin = 255;
            for (; bin >= 0; bin--) {
                c += hist[bin];
                if (c >= kth) break;
            }
            int newkth = kth - (c - hist[bin]);
            sh_kth = newkth;
            sh_prefix = prefix | ((unsigned int)bin << shift);
            if (pass == 3) sh_ties = (hist[bin] != newkth);
        }
        decided |= (255u << shift);
        __syncthreads();
    }
    unsigned int T = sh_prefix;
    int ties = sh_ties;
    for (int l = tid; l < NL; l += 256) {
        unsigned int u = su[l];
        g_mask[b * NL + l] = (unsigned char)((u > T) || (!ties && u == T));
    }
    __syncthreads();
    if (ties && tid == 0) {   // measure-zero path; exact first-index tie break
        int need = sh_kth;
        for (int l = 0; l < NL && need > 0; l++) {
            if (su[l] == T) { g_mask[b * NL + l] = 1; need--; }
        }
    }
}

// ------ B: sparse GEMM + gelu + per-tile sum (compacted, 4 rows/warp) ------
__global__ __launch_bounds__(256) void sparse_kernel(const float* __restrict__ x,
                                                     const float* __restrict__ w,
                                                     const float* __restrict__ bias) {
    __shared__ __align__(16) float ws[NC * ND];
    __shared__ __align__(16) float xs[8][4][NC];
    __shared__ float sbias[ND];
    __shared__ float ssumw[8][ND];
    __shared__ short list[64];
    __shared__ int nsel;
    int tid = threadIdx.x, wid = tid >> 5, lane = tid & 31;
    int b = blockIdx.x >> 6;       // 64 tiles per batch
    int tile = blockIdx.x & 63;
    int l0 = tile * 64;
    const float4* w4 = (const float4*)w;
    float4* ws4 = (float4*)ws;
    for (int i = tid; i < NC * ND / 4; i += 256) ws4[i] = w4[i];
    if (tid < ND) sbias[tid] = bias[tid];
    if (tid == 0) {
        int n = 0;
#pragma unroll 1
        for (int i = 0; i < 64; i++)
            if (g_mask[b * NL + l0 + i]) list[n++] = (short)(l0 + i);
        nsel = n;
    }
    __syncthreads();
    int n = nsel;
    float sum0 = 0.f, sum1 = 0.f, sum2 = 0.f, sum3 = 0.f;
#pragma unroll 1
    for (int g0 = wid * 4; g0 < n; g0 += 32) {
        // stage up to 4 selected rows into shared (each lane: 2 float4 loads)
#pragma unroll
        for (int i = 0; i < 2; i++) {
            int rr = i * 2 + (lane >> 4);
            int g = g0 + rr;
            int row = (g < n) ? (int)list[g] : (int)list[g0];
            const float4* xr = (const float4*)(x + ((size_t)b * NL + row) * NC);
            int f4 = lane & 15;
            *(float4*)&xs[wid][rr][f4 * 4] = xr[f4];
        }
        __syncwarp();
        float acc[4][4];
#pragma unroll
        for (int i = 0; i < 4; i++) { acc[i][0] = 0.f; acc[i][1] = 0.f; acc[i][2] = 0.f; acc[i][3] = 0.f; }
#pragma unroll 16
        for (int c = 0; c < NC; c++) {
            float4 wv = ws4[c * 32 + lane];
#pragma unroll
            for (int i = 0; i < 4; i++) {
                float xc = xs[wid][i][c];
                acc[i][0] = fmaf(xc, wv.x, acc[i][0]);
                acc[i][1] = fmaf(xc, wv.y, acc[i][1]);
                acc[i][2] = fmaf(xc, wv.z, acc[i][2]);
                acc[i][3] = fmaf(xc, wv.w, acc[i][3]);
            }
        }
        float b0 = sbias[lane * 4 + 0], b1 = sbias[lane * 4 + 1];
        float b2 = sbias[lane * 4 + 2], b3 = sbias[lane * 4 + 3];
#pragma unroll
        for (int i = 0; i < 4; i++) {
            if (g0 + i < n) {
                sum0 += gelu_exact(acc[i][0] + b0);
                sum1 += gelu_exact(acc[i][1] + b1);
                sum2 += gelu_exact(acc[i][2] + b2);
                sum3 += gelu_exact(acc[i][3] + b3);
            }
        }
        __syncwarp();
    }
    ssumw[wid][lane * 4 + 0] = sum0;
    ssumw[wid][lane * 4 + 1] = sum1;
    ssumw[wid][lane * 4 + 2] = sum2;
    ssumw[wid][lane * 4 + 3] = sum3;
    __syncthreads();
    if (tid < ND) {   // deterministic fixed-order cross-warp reduce
        float s = 0.f;
#pragma unroll
        for (int ww = 0; ww < 8; ww++) s += ssumw[ww][tid];
        g_part[(size_t)blockIdx.x * ND + tid] = s;
    }
}

// ---------------- B2: deterministic reduce of tile partials ----------------
__global__ void agg_reduce_kernel() {
    int b = blockIdx.x, d = threadIdx.x;
    float s = 0.f;
#pragma unroll 1
    for (int t = 0; t < 64; t++) s += g_part[(size_t)(b * 64 + t) * ND + d];
    g_agg[b * ND + d] = s;
}

// -------- C: full GEMM + broadcast agg + LayerNorm (4 rows/warp) -----------
__global__ __launch_bounds__(256) void full_kernel(const float* __restrict__ x,
                                                   const float* __restrict__ w,
                                                   const float* __restrict__ bias,
                                                   const float* __restrict__ lg,
                                                   const float* __restrict__ lb,
                                                   float* __restrict__ out) {
    __shared__ __align__(16) float ws[NC * ND];
    __shared__ __align__(16) float xs[8][4][NC];
    __shared__ float fba[ND], slg[ND], slb[ND];
    int tid = threadIdx.x, wid = tid >> 5, lane = tid & 31;
    int base = blockIdx.x * 128;       // 128 rows per block, single batch per block
    int b = base >> 12;                // base / NL
    const float4* w4 = (const float4*)w;
    float4* ws4 = (float4*)ws;
    for (int i = tid; i < NC * ND / 4; i += 256) ws4[i] = w4[i];
    if (tid < ND) {
        fba[tid] = bias[tid] + g_agg[b * ND + tid] * (1.0f / (float)NK);
        slg[tid] = lg[tid];
        slb[tid] = lb[tid];
    }
    __syncthreads();
    float fb0 = fba[lane * 4 + 0], fb1 = fba[lane * 4 + 1];
    float fb2 = fba[lane * 4 + 2], fb3 = fba[lane * 4 + 3];
    float gg0 = slg[lane * 4 + 0], gg1 = slg[lane * 4 + 1];
    float gg2 = slg[lane * 4 + 2], gg3 = slg[lane * 4 + 3];
    float bb0 = slb[lane * 4 + 0], bb1 = slb[lane * 4 + 1];
    float bb2 = slb[lane * 4 + 2], bb3 = slb[lane * 4 + 3];
#pragma unroll 1
    for (int t = 0; t < 4; t++) {
        int r0 = base + wid * 16 + t * 4;
#pragma unroll
        for (int i = 0; i < 2; i++) {
            int rr = i * 2 + (lane >> 4);
            const float4* xr = (const float4*)(x + (size_t)(r0 + rr) * NC);
            int f4 = lane & 15;
            *(float4*)&xs[wid][rr][f4 * 4] = xr[f4];
        }
        __syncwarp();
        float acc[4][4];
#pragma unroll
        for (int i = 0; i < 4; i++) { acc[i][0] = 0.f; acc[i][1] = 0.f; acc[i][2] = 0.f; acc[i][3] = 0.f; }
#pragma unroll 16
        for (int c = 0; c < NC; c++) {
            float4 wv = ws4[c * 32 + lane];
#pragma unroll
            for (int i = 0; i < 4; i++) {
                float xc = xs[wid][i][c];
                acc[i][0] = fmaf(xc, wv.x, acc[i][0]);
                acc[i][1] = fmaf(xc, wv.y, acc[i][1]);
                acc[i][2] = fmaf(xc, wv.z, acc[i][2]);
                acc[i][3] = fmaf(xc, wv.w, acc[i][3]);
            }
        }
        __syncwarp();
#pragma unroll
        for (int i = 0; i < 4; i++) {
            float h0 = acc[i][0] + fb0;
            float h1 = acc[i][1] + fb1;
            float h2 = acc[i][2] + fb2;
            float h3 = acc[i][3] + fb3;
            float ps = (h0 + h1) + (h2 + h3);
            float pq = fmaf(h0, h0, fmaf(h1, h1, fmaf(h2, h2, h3 * h3)));
#pragma unroll
            for (int off = 16; off; off >>= 1) {
                ps += __shfl_xor_sync(0xffffffffu, ps, off);
                pq += __shfl_xor_sync(0xffffffffu, pq, off);
            }
            float mu = ps * (1.0f / 128.0f);
            float var = pq * (1.0f / 128.0f) - mu * mu;
            float rs = rsqrtf(var + 1e-5f);
            float4 o;
            o.x = (h0 - mu) * rs * gg0 + bb0;
            o.y = (h1 - mu) * rs * gg1 + bb1;
            o.z = (h2 - mu) * rs * gg2 + bb2;
            o.w = (h3 - mu) * rs * gg3 + bb3;
            ((float4*)(out + (size_t)(r0 + i) * ND))[lane] = o;
        }
    }
}

// ---------------------------------------------------------------------------
extern "C" void kernel_launch(void* const* d_in, const int* in_sizes, int n_in,
                              void* d_out, int out_size) {
    const float* x        = (const float*)d_in[0];
    const float* score_w  = (const float*)d_in[1];
    const float* score_b  = (const float*)d_in[2];
    const float* sparse_w = (const float*)d_in[3];
    const float* sparse_b = (const float*)d_in[4];
    const float* full_w   = (const float*)d_in[5];
    const float* full_b   = (const float*)d_in[6];
    const float* ln_g     = (const float*)d_in[7];
    const float* ln_b     = (const float*)d_in[8];
    float* out = (float*)d_out;

    score_kernel<<<NB * NL / 256, 256>>>(x, score_w, score_b);
    select_kernel<<<NB, 256>>>();
    sparse_kernel<<<NB * 64, 256>>>(x, sparse_w, sparse_b);
    agg_reduce_kernel<<<NB, ND>>>();
    full_kernel<<<NB * NL / 128, 256>>>(x, full_w, full_b, ln_g, ln_b, out);
}

// round 2
// speedup vs baseline: 1.1078x; 1.1078x over previous
#include <cuda_runtime.h>
#include <math.h>

// Problem dims
#define NB 32
#define NL 4096
#define NC 64
#define ND 128
#define NK 2048   // TOPK = L/2

// ---------------- device scratch (no allocations allowed) ----------------
__device__ unsigned int  g_su[NB * NL];        // order-transformed scores
__device__ unsigned char g_mask[NB * NL];      // selected rows
__device__ float         g_part[NB * 64 * ND]; // per-(batch,tile) partial sums
__device__ float         g_agg[NB * ND];       // per-batch gelu sums

// order-preserving float -> uint (ascending)
__device__ __forceinline__ unsigned int f2u(float f) {
    unsigned int b = __float_as_uint(f);
    return (b & 0x80000000u) ? ~b : (b | 0x80000000u);
}

__device__ __forceinline__ float gelu_exact(float h) {
    return 0.5f * h * (1.0f + erff(h * 0.70710678118654752440f));
}

// ---------------- A1: scores = x . score_w + score_b -----------------------
__global__ __launch_bounds__(256) void score_kernel(const float* __restrict__ x,
                                                    const float* __restrict__ sw,
                                                    const float* __restrict__ sb) {
    __shared__ float s_w[NC];
    if (threadIdx.x < NC) s_w[threadIdx.x] = sw[threadIdx.x];
    __syncthreads();
    int r = blockIdx.x * 256 + threadIdx.x;   // 0..131071
    const float4* xr = (const float4*)(x + (size_t)r * NC);
    float acc = 0.f;
#pragma unroll
    for (int i = 0; i < 16; i++) {
        float4 v = xr[i];
        acc = fmaf(v.x, s_w[4 * i + 0], acc);
        acc = fmaf(v.y, s_w[4 * i + 1], acc);
        acc = fmaf(v.z, s_w[4 * i + 2], acc);
        acc = fmaf(v.w, s_w[4 * i + 3], acc);
    }
    g_su[r] = f2u(acc + sb[0]);
}

// ---------------- A2: per-batch exact top-NK selection (radix select) ------
__global__ __launch_bounds__(256) void select_kernel() {
    __shared__ unsigned int su[NL];
    __shared__ int hist[256];
    __shared__ unsigned int sh_prefix;
    __shared__ int sh_kth;
    __shared__ int sh_ties;
    int b = blockIdx.x;
    int tid = threadIdx.x;
    for (int l = tid; l < NL; l += 256) su[l] = g_su[b * NL + l];
    if (tid == 0) { sh_prefix = 0u; sh_kth = NK; sh_ties = 0; }
    __syncthreads();
    unsigned int decided = 0u;
    for (int pass = 0; pass < 4; pass++) {
        int shift = 24 - pass * 8;
        hist[tid] = 0;
        __syncthreads();
        unsigned int prefix = sh_prefix;
        for (int l = tid; l < NL; l += 256) {
            unsigned int u = su[l];
            bool p = ((u & decided) == prefix);
            // non-participants get unique sentinel bins -> singleton groups
            unsigned int bin = p ? ((u >> shift) & 255u) : (0x1000u + (unsigned)(tid & 31));
            unsigned int grp = __match_any_sync(0xffffffffu, bin);
            int leader = __ffs(grp) - 1;
            if (p && (tid & 31) == leader) atomicAdd(&hist[bin], __popc(grp));
        }
        __syncthreads();
        if (tid == 0) {
            int kth = sh_kth;
            int c = 0; int bin = 255;
            for (; bin >= 0; bin--) {
                c += hist[bin];
                if (c >= kth) break;
            }
            int newkth = kth - (c - hist[bin]);
            sh_kth = newkth;
            sh_prefix = prefix | ((unsigned int)bin << shift);
            if (pass == 3) sh_ties = (hist[bin] != newkth);
        }
        decided |= (255u << shift);
        __syncthreads();
    }
    unsigned int T = sh_prefix;
    int ties = sh_ties;
    for (int l = tid; l < NL; l += 256) {
        unsigned int u = su[l];
        g_mask[b * NL + l] = (unsigned char)((u > T) || (!ties && u == T));
    }
    __syncthreads();
    if (ties && tid == 0) {   // measure-zero path; exact first-index tie break
        int need = sh_kth;
        for (int l = 0; l < NL && need > 0; l++) {
            if (su[l] == T) { g_mask[b * NL + l] = 1; need--; }
        }
    }
}

// ------ B: sparse GEMM + gelu + per-tile sum (compacted, 4 rows/warp) ------
__global__ __launch_bounds__(256) void sparse_kernel(const float* __restrict__ x,
                                                     const float* __restrict__ w,
                                                     const float* __restrict__ bias) {
    __shared__ __align__(16) float ws[NC * ND];
    __shared__ __align__(16) float xs[8][4][NC];
    __shared__ float sbias[ND];
    __shared__ float ssumw[8][ND];
    __shared__ short list[64];
    __shared__ int nsel;
    int tid = threadIdx.x, wid = tid >> 5, lane = tid & 31;
    int b = blockIdx.x >> 6;       // 64 tiles per batch
    int tile = blockIdx.x & 63;
    int l0 = tile * 64;
    const float4* w4 = (const float4*)w;
    float4* ws4 = (float4*)ws;
    for (int i = tid; i < NC * ND / 4; i += 256) ws4[i] = w4[i];
    if (tid < ND) sbias[tid] = bias[tid];
    if (tid == 0) {
        int n = 0;
#pragma unroll 1
        for (int i = 0; i < 64; i++)
            if (g_mask[b * NL + l0 + i]) list[n++] = (short)(l0 + i);
        nsel = n;
    }
    __syncthreads();
    int n = nsel;
    float sum0 = 0.f, sum1 = 0.f, sum2 = 0.f, sum3 = 0.f;
#pragma unroll 1
    for (int g0 = wid * 4; g0 < n; g0 += 32) {
        // stage up to 4 selected rows into shared (each lane: 2 float4 loads)
#pragma unroll
        for (int i = 0; i < 2; i++) {
            int rr = i * 2 + (lane >> 4);
            int g = g0 + rr;
            int row = (g < n) ? (int)list[g] : (int)list[g0];
            const float4* xr = (const float4*)(x + ((size_t)b * NL + row) * NC);
            int f4 = lane & 15;
            *(float4*)&xs[wid][rr][f4 * 4] = xr[f4];
        }
        __syncwarp();
        float acc[4][4];
#pragma unroll
        for (int i = 0; i < 4; i++) { acc[i][0] = 0.f; acc[i][1] = 0.f; acc[i][2] = 0.f; acc[i][3] = 0.f; }
        // 4-c chunks: x via one broadcast LDS.128 per row, W via vec LDS.128
#pragma unroll
        for (int c4 = 0; c4 < NC / 4; c4++) {
            float4 xr0 = *(const float4*)&xs[wid][0][c4 * 4];
            float4 xr1 = *(const float4*)&xs[wid][1][c4 * 4];
            float4 xr2 = *(const float4*)&xs[wid][2][c4 * 4];
            float4 xr3 = *(const float4*)&xs[wid][3][c4 * 4];
            const float* xf0 = (const float*)&xr0;
            const float* xf1 = (const float*)&xr1;
            const float* xf2 = (const float*)&xr2;
            const float* xf3 = (const float*)&xr3;
#pragma unroll
            for (int cc = 0; cc < 4; cc++) {
                float4 wv = ws4[(c4 * 4 + cc) * 32 + lane];
                acc[0][0] = fmaf(xf0[cc], wv.x, acc[0][0]);
                acc[0][1] = fmaf(xf0[cc], wv.y, acc[0][1]);
                acc[0][2] = fmaf(xf0[cc], wv.z, acc[0][2]);
                acc[0][3] = fmaf(xf0[cc], wv.w, acc[0][3]);
                acc[1][0] = fmaf(xf1[cc], wv.x, acc[1][0]);
                acc[1][1] = fmaf(xf1[cc], wv.y, acc[1][1]);
                acc[1][2] = fmaf(xf1[cc], wv.z, acc[1][2]);
                acc[1][3] = fmaf(xf1[cc], wv.w, acc[1][3]);
                acc[2][0] = fmaf(xf2[cc], wv.x, acc[2][0]);
                acc[2][1] = fmaf(xf2[cc], wv.y, acc[2][1]);
                acc[2][2] = fmaf(xf2[cc], wv.z, acc[2][2]);
                acc[2][3] = fmaf(xf2[cc], wv.w, acc[2][3]);
                acc[3][0] = fmaf(xf3[cc], wv.x, acc[3][0]);
                acc[3][1] = fmaf(xf3[cc], wv.y, acc[3][1]);
                acc[3][2] = fmaf(xf3[cc], wv.z, acc[3][2]);
                acc[3][3] = fmaf(xf3[cc], wv.w, acc[3][3]);
            }
        }
        float b0 = sbias[lane * 4 + 0], b1 = sbias[lane * 4 + 1];
        float b2 = sbias[lane * 4 + 2], b3 = sbias[lane * 4 + 3];
#pragma unroll
        for (int i = 0; i < 4; i++) {
            if (g0 + i < n) {
                sum0 += gelu_exact(acc[i][0] + b0);
                sum1 += gelu_exact(acc[i][1] + b1);
                sum2 += gelu_exact(acc[i][2] + b2);
                sum3 += gelu_exact(acc[i][3] + b3);
            }
        }
        __syncwarp();
    }
    ssumw[wid][lane * 4 + 0] = sum0;
    ssumw[wid][lane * 4 + 1] = sum1;
    ssumw[wid][lane * 4 + 2] = sum2;
    ssumw[wid][lane * 4 + 3] = sum3;
    __syncthreads();
    if (tid < ND) {   // deterministic fixed-order cross-warp reduce
        float s = 0.f;
#pragma unroll
        for (int ww = 0; ww < 8; ww++) s += ssumw[ww][tid];
        g_part[(size_t)blockIdx.x * ND + tid] = s;
    }
}

// ---------------- B2: deterministic reduce of tile partials ----------------
// Full unroll -> 64 independent LDGs in flight (MLP~high), was MLP=1 / 32us.
__global__ void agg_reduce_kernel() {
    int b = blockIdx.x, d = threadIdx.x;
    float s = 0.f;
#pragma unroll
    for (int t = 0; t < 64; t++) s += g_part[(size_t)(b * 64 + t) * ND + d];
    g_agg[b * ND + d] = s;
}

// -------- C: full GEMM + broadcast agg + LayerNorm (4 rows/warp) -----------
__global__ __launch_bounds__(256) void full_kernel(const float* __restrict__ x,
                                                   const float* __restrict__ w,
                                                   const float* __restrict__ bias,
                                                   const float* __restrict__ lg,
                                                   const float* __restrict__ lb,
                                                   float* __restrict__ out) {
    __shared__ __align__(16) float ws[NC * ND];
    __shared__ __align__(16) float xs[8][4][NC];
    __shared__ float fba[ND], slg[ND], slb[ND];
    int tid = threadIdx.x, wid = tid >> 5, lane = tid & 31;
    int base = blockIdx.x * 128;       // 128 rows per block, single batch per block
    int b = base >> 12;                // base / NL
    const float4* w4 = (const float4*)w;
    float4* ws4 = (float4*)ws;
    for (int i = tid; i < NC * ND / 4; i += 256) ws4[i] = w4[i];
    if (tid < ND) {
        fba[tid] = bias[tid] + g_agg[b * ND + tid] * (1.0f / (float)NK);
        slg[tid] = lg[tid];
        slb[tid] = lb[tid];
    }
    __syncthreads();
    float fb0 = fba[lane * 4 + 0], fb1 = fba[lane * 4 + 1];
    float fb2 = fba[lane * 4 + 2], fb3 = fba[lane * 4 + 3];
    float gg0 = slg[lane * 4 + 0], gg1 = slg[lane * 4 + 1];
    float gg2 = slg[lane * 4 + 2], gg3 = slg[lane * 4 + 3];
    float bb0 = slb[lane * 4 + 0], bb1 = slb[lane * 4 + 1];
    float bb2 = slb[lane * 4 + 2], bb3 = slb[lane * 4 + 3];
#pragma unroll 1
    for (int t = 0; t < 4; t++) {
        int r0 = base + wid * 16 + t * 4;
#pragma unroll
        for (int i = 0; i < 2; i++) {
            int rr = i * 2 + (lane >> 4);
            const float4* xr = (const float4*)(x + (size_t)(r0 + rr) * NC);
            int f4 = lane & 15;
            *(float4*)&xs[wid][rr][f4 * 4] = xr[f4];
        }
        __syncwarp();
        float acc[4][4];
#pragma unroll
        for (int i = 0; i < 4; i++) { acc[i][0] = 0.f; acc[i][1] = 0.f; acc[i][2] = 0.f; acc[i][3] = 0.f; }
#pragma unroll
        for (int c4 = 0; c4 < NC / 4; c4++) {
            float4 xr0 = *(const float4*)&xs[wid][0][c4 * 4];
            float4 xr1 = *(const float4*)&xs[wid][1][c4 * 4];
            float4 xr2 = *(const float4*)&xs[wid][2][c4 * 4];
            float4 xr3 = *(const float4*)&xs[wid][3][c4 * 4];
            const float* xf0 = (const float*)&xr0;
            const float* xf1 = (const float*)&xr1;
            const float* xf2 = (const float*)&xr2;
            const float* xf3 = (const float*)&xr3;
#pragma unroll
            for (int cc = 0; cc < 4; cc++) {
                float4 wv = ws4[(c4 * 4 + cc) * 32 + lane];
                acc[0][0] = fmaf(xf0[cc], wv.x, acc[0][0]);
                acc[0][1] = fmaf(xf0[cc], wv.y, acc[0][1]);
                acc[0][2] = fmaf(xf0[cc], wv.z, acc[0][2]);
                acc[0][3] = fmaf(xf0[cc], wv.w, acc[0][3]);
                acc[1][0] = fmaf(xf1[cc], wv.x, acc[1][0]);
                acc[1][1] = fmaf(xf1[cc], wv.y, acc[1][1]);
                acc[1][2] = fmaf(xf1[cc], wv.z, acc[1][2]);
                acc[1][3] = fmaf(xf1[cc], wv.w, acc[1][3]);
                acc[2][0] = fmaf(xf2[cc], wv.x, acc[2][0]);
                acc[2][1] = fmaf(xf2[cc], wv.y, acc[2][1]);
                acc[2][2] = fmaf(xf2[cc], wv.z, acc[2][2]);
                acc[2][3] = fmaf(xf2[cc], wv.w, acc[2][3]);
                acc[3][0] = fmaf(xf3[cc], wv.x, acc[3][0]);
                acc[3][1] = fmaf(xf3[cc], wv.y, acc[3][1]);
                acc[3][2] = fmaf(xf3[cc], wv.z, acc[3][2]);
                acc[3][3] = fmaf(xf3[cc], wv.w, acc[3][3]);
            }
        }
        __syncwarp();
#pragma unroll
        for (int i = 0; i < 4; i++) {
            float h0 = acc[i][0] + fb0;
            float h1 = acc[i][1] + fb1;
            float h2 = acc[i][2] + fb2;
            float h3 = acc[i][3] + fb3;
            float ps = (h0 + h1) + (h2 + h3);
            float pq = fmaf(h0, h0, fmaf(h1, h1, fmaf(h2, h2, h3 * h3)));
#pragma unroll
            for (int off = 16; off; off >>= 1) {
                ps += __shfl_xor_sync(0xffffffffu, ps, off);
                pq += __shfl_xor_sync(0xffffffffu, pq, off);
            }
            float mu = ps * (1.0f / 128.0f);
            float var = pq * (1.0f / 128.0f) - mu * mu;
            float rs = rsqrtf(var + 1e-5f);
            float4 o;
            o.x = (h0 - mu) * rs * gg0 + bb0;
            o.y = (h1 - mu) * rs * gg1 + bb1;
            o.z = (h2 - mu) * rs * gg2 + bb2;
            o.w = (h3 - mu) * rs * gg3 + bb3;
            ((float4*)(out + (size_t)(r0 + i) * ND))[lane] = o;
        }
    }
}

// ---------------------------------------------------------------------------
extern "C" void kernel_launch(void* const* d_in, const int* in_sizes, int n_in,
                              void* d_out, int out_size) {
    const float* x        = (const float*)d_in[0];
    const float* score_w  = (const float*)d_in[1];
    const float* score_b  = (const float*)d_in[2];
    const float* sparse_w = (const float*)d_in[3];
    const float* sparse_b = (const float*)d_in[4];
    const float* full_w   = (const float*)d_in[5];
    const float* full_b   = (const float*)d_in[6];
    const float* ln_g     = (const float*)d_in[7];
    const float* ln_b     = (const float*)d_in[8];
    float* out = (float*)d_out;

    score_kernel<<<NB * NL / 256, 256>>>(x, score_w, score_b);
    select_kernel<<<NB, 256>>>();
    sparse_kernel<<<NB * 64, 256>>>(x, sparse_w, sparse_b);
    agg_reduce_kernel<<<NB, ND>>>();
    full_kernel<<<NB * NL / 128, 256>>>(x, full_w, full_b, ln_g, ln_b, out);
}